// round 17
// baseline (speedup 1.0000x reference)
#include <cuda_runtime.h>
#include <cuda_fp16.h>
#include <cstdint>

// QKVAttention via HMMA mma.sync. qkv [32,192,2048] fp32 -> out [32,64,2048] fp32.
// Key change this round: m32-tall warp tiles (8 warps = 2m x 4n, warp = m32xn32)
// halve smem bytes per mma (each K/V ldsm.x4 feeds 4 mma) -- the profile showed
// tensor and L1 locked at ~54% because m16 warps need 128B/cyc/SM of LDS at full
// tensor rate (= crossbar peak). 3-stage cp.async pipeline; rowsums via ALU
// HADD2 on P fragments (off the tensor pipe) + quad shuffle.

constexpr int T  = 2048;
constexpr int CH = 64;
constexpr int BM = 64;             // queries per CTA
constexpr int BN = 128;            // keys per iteration
constexpr int NITER = T / BN;
constexpr int THREADS = 256;
constexpr int RSQ = 72;            // Q smem row stride (halves)
constexpr int RSH = 136;           // K/V smem row stride (halves)
constexpr int QSZ = CH * RSQ * 2;  // 9216 B
constexpr int TSZ = CH * RSH * 2;  // 17408 B per [64][128] f16 tile
constexpr int STAGES = 3;
constexpr int SMEM_TOTAL = QSZ + STAGES * 2 * TSZ;   // 113664 B
// epilogue overlays (after final __syncthreads)
constexpr int OFF_OS = 0;                  // 4 x [64 c][68 m] f32 regions
constexpr int OSZ = 64 * 68 * 4;           // 17408 B per region
constexpr int OFF_SUM = OFF_OS + 4 * OSZ;  // sums[4][64] f32
constexpr int OFF_INV = OFF_SUM + 4 * 64 * 4;
constexpr float QSCALE = 0.18033688011112042f;  // 0.125 * log2(e)

__device__ __half g_qkv16[(size_t)32 * 192 * 2048];

__device__ __forceinline__ uint32_t s2u(const void* p) {
    uint32_t a;
    asm("{ .reg .u64 t; cvta.to.shared.u64 t, %1; cvt.u32.u64 %0, t; }" : "=r"(a) : "l"(p));
    return a;
}
__device__ __forceinline__ void ldsm4(uint32_t* r, uint32_t a) {
    asm volatile("ldmatrix.sync.aligned.m8n8.x4.shared.b16 {%0,%1,%2,%3}, [%4];"
                 : "=r"(r[0]), "=r"(r[1]), "=r"(r[2]), "=r"(r[3]) : "r"(a));
}
__device__ __forceinline__ void ldsm4t(uint32_t* r, uint32_t a) {
    asm volatile("ldmatrix.sync.aligned.m8n8.x4.trans.shared.b16 {%0,%1,%2,%3}, [%4];"
                 : "=r"(r[0]), "=r"(r[1]), "=r"(r[2]), "=r"(r[3]) : "r"(a));
}
__device__ __forceinline__ void mma16816(float* d, const uint32_t* a, const uint32_t* b) {
    asm volatile("mma.sync.aligned.m16n8k16.row.col.f32.f16.f16.f32 "
                 "{%0,%1,%2,%3}, {%4,%5,%6,%7}, {%8,%9}, {%0,%1,%2,%3};"
                 : "+f"(d[0]), "+f"(d[1]), "+f"(d[2]), "+f"(d[3])
                 : "r"(a[0]), "r"(a[1]), "r"(a[2]), "r"(a[3]), "r"(b[0]), "r"(b[1]));
}
__device__ __forceinline__ uint32_t packh2(float lo, float hi) {
    uint32_t r; asm("cvt.rn.f16x2.f32 %0, %2, %1;" : "=r"(r) : "f"(lo), "f"(hi)); return r;
}
__device__ __forceinline__ uint32_t h2ex2(uint32_t x) {
    uint32_t y; asm("ex2.approx.f16x2 %0, %1;" : "=r"(y) : "r"(x)); return y;
}
__device__ __forceinline__ uint32_t hadd2(uint32_t a, uint32_t b) {
    uint32_t r; asm("add.rn.f16x2 %0, %1, %2;" : "=r"(r) : "r"(a), "r"(b)); return r;
}
__device__ __forceinline__ float2 h2f2(uint32_t x) {
    __half2 h = *reinterpret_cast<__half2*>(&x);
    return __half22float2(h);
}
__device__ __forceinline__ void cp_tile(const __half* src, uint32_t dst_s, int tid) {
    #pragma unroll
    for (int it = 0; it < 4; ++it) {
        int idx = tid + it * 256;
        int row = idx >> 4, c16 = idx & 15;
        uint32_t d = dst_s + (row * RSH + c16 * 8) * 2;
        const void* s = src + (size_t)row * T + c16 * 8;
        asm volatile("cp.async.cg.shared.global [%0], [%1], 16;" :: "r"(d), "l"(s));
    }
}
__device__ __forceinline__ void cp_commit() {
    asm volatile("cp.async.commit_group;" ::: "memory");
}
__device__ __forceinline__ void cp_wait0() {
    asm volatile("cp.async.wait_group 0;" ::: "memory");
}
__device__ __forceinline__ void cp_wait1() {
    asm volatile("cp.async.wait_group 1;" ::: "memory");
}

// ---- pre-pass: K,V fp32 -> fp16 ----
__global__ __launch_bounds__(256)
void cvt_kernel(const float* __restrict__ qkv, __half* __restrict__ dst)
{
    size_t idx8 = ((size_t)blockIdx.x * 256 + threadIdx.x) * 8;
    size_t bt = idx8 / (128 * 2048);
    size_t rem = idx8 % (128 * 2048);
    size_t off = bt * (192 * 2048) + 64 * 2048 + rem;
    float4 f0 = *reinterpret_cast<const float4*>(qkv + off);
    float4 f1 = *reinterpret_cast<const float4*>(qkv + off + 4);
    uint4 h;
    h.x = packh2(f0.x, f0.y);
    h.y = packh2(f0.z, f0.w);
    h.z = packh2(f1.x, f1.y);
    h.w = packh2(f1.z, f1.w);
    *reinterpret_cast<uint4*>(dst + off) = h;
}

__global__ __launch_bounds__(THREADS, 1)
void attn_hmma_kernel(const float* __restrict__ qkv, float* __restrict__ out)
{
    extern __shared__ char smem[];
    const uint32_t sb = s2u(smem);
    const int tid = threadIdx.x;
    const int lane = tid & 31, w = tid >> 5;
    const int b = blockIdx.y, t0 = blockIdx.x * BM;
    const int wm = (w >> 2) * 32;          // m32 block (2 groups)
    const int wn = (w & 3) * 32;           // n32 slice (4 n-warps)
    const int stag = w & 1;                // chunk stagger

    const float* qb = qkv + (size_t)b * 3 * CH * T;
    const __half* kh = g_qkv16 + (size_t)b * 3 * CH * T + (size_t)CH * T;
    const __half* vh = kh + (size_t)CH * T;

    // ---- prologue: Q -> smem fp16 (scaled); stages 0,1 of K/V via cp.async ----
    #pragma unroll
    for (int it = 0; it < 4; ++it) {
        int idx = tid + it * 256;
        int c = idx >> 4, m4 = idx & 15;
        float4 f = *reinterpret_cast<const float4*>(qb + (size_t)c * T + t0 + m4 * 4);
        *reinterpret_cast<uint2*>(smem + (c * RSQ + m4 * 4) * 2) =
            make_uint2(packh2(f.x * QSCALE, f.y * QSCALE),
                       packh2(f.z * QSCALE, f.w * QSCALE));
    }
    cp_tile(kh, sb + QSZ, tid);
    cp_tile(vh, sb + QSZ + TSZ, tid);
    cp_commit();
    cp_tile(kh + BN, sb + QSZ + 2 * TSZ, tid);
    cp_tile(vh + BN, sb + QSZ + 3 * TSZ, tid);
    cp_commit();
    __syncthreads();   // Q visible to all warps

    const int lr = lane & 7, grp = lane >> 3;
    const int ac = lr + ((grp >= 2) ? 8 : 0);
    const int am = (grp & 1) ? 8 : 0;
    const int kc = lr + ((grp & 1) ? 8 : 0);
    const int kn = (grp >= 2) ? 8 : 0;
    const int vc = lr + ((grp >= 2) ? 8 : 0);
    const int vn = (grp & 1) ? 8 : 0;

    // ---- preload Q A-fragments: 4 k-steps x 2 m-blocks ----
    uint32_t qa[4][2][4];
    #pragma unroll
    for (int kk = 0; kk < 4; ++kk)
        #pragma unroll
        for (int mb = 0; mb < 2; ++mb)
            ldsm4t(qa[kk][mb], sb + ((kk * 16 + ac) * RSQ + wm + mb * 16 + am) * 2);

    float o[2][8][4];
    #pragma unroll
    for (int mb = 0; mb < 2; ++mb)
        #pragma unroll
        for (int j = 0; j < 8; ++j)
            o[mb][j][0] = o[mb][j][1] = o[mb][j][2] = o[mb][j][3] = 0.f;
    float rs[2][2] = {{0.f, 0.f}, {0.f, 0.f}};

    for (int i = 0; i < NITER; ++i) {
        const int stage = i % STAGES;
        const uint32_t Kb = sb + QSZ + stage * 2 * TSZ;
        const uint32_t Vb = Kb + TSZ;

        if (i == NITER - 1) cp_wait0(); else cp_wait1();   // stage i landed
        __syncthreads();   // all warps done with the buffer being overwritten next

        if (i + 2 < NITER) {   // prefetch stage i+2
            const uint32_t Pb = sb + QSZ + ((i + 2) % STAGES) * 2 * TSZ;
            cp_tile(kh + (i + 2) * BN, Pb, tid);
            cp_tile(vh + (i + 2) * BN, Pb + TSZ, tid);
            cp_commit();
        }

        #pragma unroll
        for (int ch = 0; ch < 2; ++ch) {
            const int ncol = wn + ((ch + stag) & 1) * 16;

            // ---- S chunk: m32 x n16 (each K ldsm feeds 4 mma) ----
            float s[2][2][4];
            #pragma unroll
            for (int mb = 0; mb < 2; ++mb)
                #pragma unroll
                for (int h = 0; h < 2; ++h)
                    s[mb][h][0] = s[mb][h][1] = s[mb][h][2] = s[mb][h][3] = 0.f;
            #pragma unroll
            for (int kk = 0; kk < 4; ++kk) {
                uint32_t kb4[4];
                ldsm4t(kb4, Kb + ((kk * 16 + kc) * RSH + ncol + kn) * 2);
                mma16816(s[0][0], qa[kk][0], kb4);
                mma16816(s[0][1], qa[kk][0], kb4 + 2);
                mma16816(s[1][0], qa[kk][1], kb4);
                mma16816(s[1][1], qa[kk][1], kb4 + 2);
            }

            // ---- P = ex2(S); rowsums via HADD2 (ALU, off tensor pipe) ----
            uint32_t pa[2][4];
            #pragma unroll
            for (int mb = 0; mb < 2; ++mb) {
                pa[mb][0] = h2ex2(packh2(s[mb][0][0], s[mb][0][1]));
                pa[mb][1] = h2ex2(packh2(s[mb][0][2], s[mb][0][3]));
                pa[mb][2] = h2ex2(packh2(s[mb][1][0], s[mb][1][1]));
                pa[mb][3] = h2ex2(packh2(s[mb][1][2], s[mb][1][3]));
                float2 f0 = h2f2(hadd2(pa[mb][0], pa[mb][2]));   // row r0 partials
                float2 f1 = h2f2(hadd2(pa[mb][1], pa[mb][3]));   // row r1 partials
                rs[mb][0] += f0.x + f0.y;
                rs[mb][1] += f1.x + f1.y;
            }

            // ---- PV chunk: O += P[:, n16] V^T (each V ldsm feeds 4 mma) ----
            #pragma unroll
            for (int cc = 0; cc < 4; ++cc) {
                uint32_t vb4[4];
                ldsm4(vb4, Vb + ((cc * 16 + vc) * RSH + ncol + vn) * 2);
                mma16816(o[0][2 * cc],     pa[0], vb4);
                mma16816(o[0][2 * cc + 1], pa[0], vb4 + 2);
                mma16816(o[1][2 * cc],     pa[1], vb4);
                mma16816(o[1][2 * cc + 1], pa[1], vb4 + 2);
            }
        }
    }
    __syncthreads();   // K/V stage buffers dead; overlays become safe

    // ---- epilogue: 4-way n-slice reduction + normalize + store ----
    {
        // quad-reduce row sums (each quad lane held different columns)
        #pragma unroll
        for (int mb = 0; mb < 2; ++mb)
            #pragma unroll
            for (int k = 0; k < 2; ++k) {
                rs[mb][k] += __shfl_xor_sync(0xffffffffu, rs[mb][k], 1);
                rs[mb][k] += __shfl_xor_sync(0xffffffffu, rs[mb][k], 2);
            }

        float* Os = reinterpret_cast<float*>(smem + OFF_OS + (w & 3) * OSZ);
        float* SU = reinterpret_cast<float*>(smem + OFF_SUM) + (w & 3) * 64;
        const int cq = 2 * (lane & 3);
        #pragma unroll
        for (int mb = 0; mb < 2; ++mb) {
            const int r0 = wm + mb * 16 + (lane >> 2), r1 = r0 + 8;
            #pragma unroll
            for (int j = 0; j < 8; ++j) {
                const int c = (j >> 1) * 16 + (j & 1) * 8 + cq;
                Os[c * 68 + r0]       = o[mb][j][0];
                Os[(c + 1) * 68 + r0] = o[mb][j][1];
                Os[c * 68 + r1]       = o[mb][j][2];
                Os[(c + 1) * 68 + r1] = o[mb][j][3];
            }
            if ((lane & 3) == 0) {
                SU[r0] = rs[mb][0];
                SU[r1] = rs[mb][1];
            }
        }
        __syncthreads();

        float* S0 = reinterpret_cast<float*>(smem + OFF_SUM);
        float* IV = reinterpret_cast<float*>(smem + OFF_INV);
        if (tid < 64)
            IV[tid] = 1.0f / (S0[tid] + S0[64 + tid] + S0[128 + tid] + S0[192 + tid]);
        __syncthreads();

        const float* O0 = reinterpret_cast<const float*>(smem + OFF_OS);
        float* ob = out + (size_t)b * CH * T;
        #pragma unroll
        for (int it = 0; it < 4; ++it) {
            int idx = tid + it * 256;
            int c = idx >> 4, m4 = idx & 15;
            float4 a0 = *reinterpret_cast<const float4*>(&O0[(0 * 64 * 68) + c * 68 + m4 * 4]);
            float4 a1 = *reinterpret_cast<const float4*>(&O0[(1 * 64 * 68) + c * 68 + m4 * 4]);
            float4 a2 = *reinterpret_cast<const float4*>(&O0[(2 * 64 * 68) + c * 68 + m4 * 4]);
            float4 a3 = *reinterpret_cast<const float4*>(&O0[(3 * 64 * 68) + c * 68 + m4 * 4]);
            float4 iv = *reinterpret_cast<const float4*>(&IV[m4 * 4]);
            float4 r = make_float4((a0.x + a1.x + a2.x + a3.x) * iv.x,
                                   (a0.y + a1.y + a2.y + a3.y) * iv.y,
                                   (a0.z + a1.z + a2.z + a3.z) * iv.z,
                                   (a0.w + a1.w + a2.w + a3.w) * iv.w);
            *reinterpret_cast<float4*>(ob + (size_t)c * T + t0 + m4 * 4) = r;
        }
    }
}

extern "C" void kernel_launch(void* const* d_in, const int* in_sizes, int n_in,
                              void* d_out, int out_size)
{
    (void)in_sizes; (void)n_in; (void)out_size;
    const float* qkv = (const float*)d_in[0];
    float* out = (float*)d_out;

    __half* scratch = nullptr;
    cudaGetSymbolAddress((void**)&scratch, g_qkv16);

    cudaFuncSetAttribute(attn_hmma_kernel,
                         cudaFuncAttributeMaxDynamicSharedMemorySize, SMEM_TOTAL);

    cvt_kernel<<<4096, 256>>>(qkv, scratch);
    dim3 grid(T / BM, 32);
    attn_hmma_kernel<<<grid, THREADS, SMEM_TOTAL>>>(qkv, out);
}